// round 5
// baseline (speedup 1.0000x reference)
#include <cuda_runtime.h>
#include <cuda_bf16.h>
#include <math.h>
#include <stdint.h>

#define BATCH   2
#define SEQ     2048
#define DMODEL  2048
#define NHEADS  32
#define DSTATE  64
#define HEADDIM 64
#define DCONV   4
#define INTERSZ 5504
#define DINNER  DMODEL
#define CONVDIM (DINNER + 2*NHEADS*DSTATE)              /* 6144 */
#define DPROJ   (2*DINNER + 2*NHEADS*DSTATE + NHEADS)   /* 8224 */
#define MROWS   (BATCH*SEQ)                             /* 4096 */

// ---------------- scratch ----------------
__device__ float g_xnorm[(size_t)MROWS * DMODEL];
__device__ float g_zx   [(size_t)MROWS * DPROJ];
__device__ float g_xbc  [(size_t)MROWS * CONVDIM];
__device__ float g_gated[(size_t)MROWS * DMODEL];
__device__ float g_res2 [(size_t)MROWS * DMODEL];
__device__ float g_gatef[(size_t)MROWS * INTERSZ];
__device__ float g_upf  [(size_t)MROWS * INTERSZ];

static __device__ __forceinline__ uint32_t smem_u32(const void* p) {
    uint32_t a;
    asm("{ .reg .u64 t; cvta.to.shared.u64 t, %1; cvt.u32.u64 %0, t; }" : "=r"(a) : "l"(p));
    return a;
}

#define LDSM_X4(r, addr) \
    asm volatile("ldmatrix.sync.aligned.m8n8.x4.shared.b16 {%0,%1,%2,%3}, [%4];" \
        : "=r"((r)[0]), "=r"((r)[1]), "=r"((r)[2]), "=r"((r)[3]) : "r"(addr))

#define MMA16816(c, a, b0, b1) \
    asm volatile("mma.sync.aligned.m16n8k16.row.col.f32.bf16.bf16.f32 " \
        "{%0,%1,%2,%3}, {%4,%5,%6,%7}, {%8,%9}, {%0,%1,%2,%3};" \
        : "+f"((c)[0]), "+f"((c)[1]), "+f"((c)[2]), "+f"((c)[3]) \
        : "r"((a)[0]), "r"((a)[1]), "r"((a)[2]), "r"((a)[3]), "r"(b0), "r"(b1))

// convert 8 fp32 -> 4 u32 (bf16x2 hi) + 4 u32 (bf16x2 lo)
static __device__ __forceinline__ void cvt8(const float* v, uint32_t* hi, uint32_t* lo) {
#pragma unroll
    for (int j = 0; j < 4; j++) {
        __nv_bfloat162 h = __float22bfloat162_rn(make_float2(v[2*j], v[2*j+1]));
        float g0 = __bfloat162float(h.x), g1 = __bfloat162float(h.y);
        __nv_bfloat162 l = __float22bfloat162_rn(make_float2(v[2*j]-g0, v[2*j+1]-g1));
        hi[j] = *(uint32_t*)&h; lo[j] = *(uint32_t*)&l;
    }
}
#define STSV4(addr, r) \
    asm volatile("st.shared.v4.b32 [%0], {%1,%2,%3,%4};" :: "r"(addr), \
        "r"((r)[0]), "r"((r)[1]), "r"((r)[2]), "r"((r)[3]))

// ================= bf16x3 GEMM on mma.sync, 128x256x32 tile =================
// smem stage: Ahi(10240) | Alo(10240) | Bhi(20480) | Blo(20480) = 61440 B, x2 stages.
// rows are 40 bf16 (80 B) wide -> conflict-free ldmatrix.
#define OFF_AL 10240
#define OFF_BH 20480
#define OFF_BL 40960
#define STAGE  61440
#define GSMEM  (2*STAGE)

__global__ __launch_bounds__(256, 1) void gemm_mma(
    const float* __restrict__ A, const float* __restrict__ Bw,
    float* __restrict__ C, const float* __restrict__ addv,
    int N, int K, int addflag)
{
    extern __shared__ char sm[];
    const int tid  = threadIdx.x;
    const int bm   = blockIdx.x * 128;
    const int bn   = blockIdx.y * 256;
    const int warp = tid >> 5, lane = tid & 31;
    const int wm = warp >> 2, wn = warp & 3;       // 2 x 4 warps, warp tile 64x64
    const uint32_t sbase = smem_u32(sm);

    // staging: A: thread -> (row=tid>>1, col16=(tid&1)*16); B: thread -> row=tid, cols 0..31
    const int arow = tid >> 1;
    const int acol = (tid & 1) << 4;
    const float* aG = A + (size_t)(bm + arow) * K + acol;
    const bool  bok = (bn + tid) < N;
    const float* bG = Bw + (size_t)(bok ? (bn + tid) : 0) * K;
    const uint32_t stA = (uint32_t)(arow * 80 + acol * 2);
    const uint32_t stB = (uint32_t)(tid * 80);

    float acc[4][8][4];
#pragma unroll
    for (int i = 0; i < 4; i++)
#pragma unroll
        for (int j = 0; j < 8; j++)
#pragma unroll
            for (int r = 0; r < 4; r++) acc[i][j][r] = 0.f;

    float fa[16], fb[32];
    // ---- prologue: slab 0 ----
#pragma unroll
    for (int v = 0; v < 4; v++) *(float4*)&fa[v*4] = *(const float4*)(aG + v*4);
#pragma unroll
    for (int v = 0; v < 8; v++)
        *(float4*)&fb[v*4] = bok ? *(const float4*)(bG + v*4) : make_float4(0.f,0.f,0.f,0.f);
    {
        uint32_t h[4], l[4];
        cvt8(fa,     h, l); STSV4(sbase + stA,          h); STSV4(sbase + OFF_AL + stA,      l);
        cvt8(fa + 8, h, l); STSV4(sbase + stA + 16,     h); STSV4(sbase + OFF_AL + stA + 16, l);
#pragma unroll
        for (int c = 0; c < 4; c++) {
            cvt8(fb + c*8, h, l);
            STSV4(sbase + OFF_BH + stB + c*16, h);
            STSV4(sbase + OFF_BL + stB + c*16, l);
        }
    }
    __syncthreads();

    const int lrow  = lane & 15;
    const int lcolb = (lane >> 4) << 3;
    const int nslab = K / 32;

    for (int s = 0; s < nslab; s++) {
        const uint32_t stb = sbase + (uint32_t)(s & 1) * STAGE;
        const uint32_t ntb = sbase + (uint32_t)((s + 1) & 1) * STAGE;
        const bool pre = (s + 1 < nslab);
        if (pre) {
            const int k0 = (s + 1) * 32;
#pragma unroll
            for (int v = 0; v < 4; v++) *(float4*)&fa[v*4] = *(const float4*)(aG + k0 + v*4);
#pragma unroll
            for (int v = 0; v < 8; v++)
                *(float4*)&fb[v*4] = bok ? *(const float4*)(bG + k0 + v*4)
                                         : make_float4(0.f,0.f,0.f,0.f);
        }
#pragma unroll
        for (int ks = 0; ks < 2; ks++) {
            const int k0 = ks * 16;
            uint32_t bh[4][4], bl[4][4];
#pragma unroll
            for (int bt = 0; bt < 4; bt++) {
                const uint32_t off = (uint32_t)(((wn*64 + bt*16 + lrow) * 40 + k0 + lcolb) * 2);
                LDSM_X4(bh[bt], stb + OFF_BH + off);
                LDSM_X4(bl[bt], stb + OFF_BL + off);
            }
#pragma unroll
            for (int mt = 0; mt < 4; mt++) {
                uint32_t ah[4], al[4];
                const uint32_t off = (uint32_t)(((wm*64 + mt*16 + lrow) * 40 + k0 + lcolb) * 2);
                LDSM_X4(ah, stb + off);
                LDSM_X4(al, stb + OFF_AL + off);
#pragma unroll
                for (int nt = 0; nt < 8; nt++) {
                    const int bt = nt >> 1, sel = nt & 1;
                    const uint32_t b0h = bh[bt][sel], b1h = bh[bt][2+sel];
                    const uint32_t b0l = bl[bt][sel], b1l = bl[bt][2+sel];
                    MMA16816(acc[mt][nt], ah, b0h, b1h);
                    MMA16816(acc[mt][nt], al, b0h, b1h);
                    MMA16816(acc[mt][nt], ah, b0l, b1l);
                }
            }
            if (ks == 0 && pre) {   // mid-slab: convert + store next stage (frees staging regs)
                uint32_t h[4], l[4];
                cvt8(fa,     h, l); STSV4(ntb + stA,          h); STSV4(ntb + OFF_AL + stA,      l);
                cvt8(fa + 8, h, l); STSV4(ntb + stA + 16,     h); STSV4(ntb + OFF_AL + stA + 16, l);
#pragma unroll
                for (int c = 0; c < 4; c++) {
                    cvt8(fb + c*8, h, l);
                    STSV4(ntb + OFF_BH + stB + c*16, h);
                    STSV4(ntb + OFF_BL + stB + c*16, l);
                }
            }
        }
        __syncthreads();
    }

    // ---- epilogue ----
    const int g  = lane >> 2;
    const int t4 = lane & 3;
#pragma unroll
    for (int mt = 0; mt < 4; mt++) {
        const int row = bm + wm*64 + mt*16 + g;
#pragma unroll
        for (int nt = 0; nt < 8; nt++) {
            const int col = bn + wn*64 + nt*8 + t4*2;
            if (col < N) {
                float2 v0 = make_float2(acc[mt][nt][0], acc[mt][nt][1]);
                float2 v1 = make_float2(acc[mt][nt][2], acc[mt][nt][3]);
                const size_t i0 = (size_t)row * N + col;
                const size_t i1 = (size_t)(row + 8) * N + col;
                if (addflag) {
                    const float2 a0 = *(const float2*)(addv + i0);
                    const float2 a1 = *(const float2*)(addv + i1);
                    v0.x += a0.x; v0.y += a0.y; v1.x += a1.x; v1.y += a1.y;
                }
                *(float2*)(C + i0) = v0;
                *(float2*)(C + i1) = v1;
            }
        }
    }
}

// ---------------- RMSNorm (optionally * mask) ----------------
__global__ void rmsnorm_kernel(const float* __restrict__ x,
                               const float* __restrict__ w,
                               const float* __restrict__ mask,
                               float* __restrict__ out)
{
    const int m = blockIdx.x;
    const float* row = x + (size_t)m * DMODEL;
    float s = 0.f;
    for (int i = threadIdx.x; i < DMODEL; i += 256) { float v = row[i]; s += v * v; }
#pragma unroll
    for (int o = 16; o > 0; o >>= 1) s += __shfl_xor_sync(0xffffffffu, s, o);
    __shared__ float red[8];
    const int lane = threadIdx.x & 31, wid = threadIdx.x >> 5;
    if (lane == 0) red[wid] = s;
    __syncthreads();
    if (wid == 0) {
        s = (lane < 8) ? red[lane] : 0.f;
#pragma unroll
        for (int o = 4; o > 0; o >>= 1) s += __shfl_xor_sync(0xffffffffu, s, o);
        if (lane == 0) red[0] = s;
    }
    __syncthreads();
    const float inv = rsqrtf(red[0] * (1.0f / (float)DMODEL) + 1e-6f);
    const float mk = mask ? mask[m] : 1.f;
    for (int i = threadIdx.x; i < DMODEL; i += 256)
        out[(size_t)m * DMODEL + i] = row[i] * inv * w[i] * mk;
}

// ---------------- causal depthwise conv1d ----------------
__global__ void conv_kernel(const float* __restrict__ zx,
                            const float* __restrict__ cw,
                            const float* __restrict__ cb,
                            float* __restrict__ xbc)
{
    const int m = blockIdx.x;
    const int t = m & (SEQ - 1);
    for (int c = threadIdx.x; c < CONVDIM; c += 256) {
        float acc = cb[c];
#pragma unroll
        for (int j = 0; j < DCONV; j++) {
            const int tt = t - (DCONV - 1) + j;
            if (tt >= 0)
                acc += cw[c * DCONV + j] *
                       zx[(size_t)(m - (DCONV - 1) + j) * DPROJ + DINNER + c];
        }
        xbc[(size_t)m * CONVDIM + c] = acc;
    }
}

// ---------------- sequential SSM scan + gating ----------------
#define CHK 8
#define TVALS 257
__global__ __launch_bounds__(256) void scan_kernel(
    const float* __restrict__ xbc, const float* __restrict__ zx,
    const float* __restrict__ Dv, const float* __restrict__ zb,
    float* __restrict__ gated)
{
    const int bh = blockIdx.x;
    const int b = bh >> 5;
    const int h = bh & 31;
    const int tid = threadIdx.x;
    const int p = tid >> 2;
    const int q = tid & 3;
    const int n0 = q << 4;

    __shared__ float sd[2][CHK * TVALS];

    int lts[9], loff[9], lkind[9], lsh[9];
    bool lvalid[9];
#pragma unroll
    for (int k = 0; k < 9; k++) {
        const int e = tid + k * 256;
        lvalid[k] = (e < CHK * TVALS);
        const int tsub = e / TVALS;
        const int j = e - tsub * TVALS;
        lts[k] = tsub; lsh[k] = e;
        if (j < 64)        { lkind[k] = 0; loff[k] = h * HEADDIM + j; }
        else if (j < 128)  { lkind[k] = 0; loff[k] = DINNER + h * DSTATE + (j - 64); }
        else if (j < 192)  { lkind[k] = 0; loff[k] = DINNER + NHEADS * DSTATE + h * DSTATE + (j - 128); }
        else if (j < 256)  { lkind[k] = 1; loff[k] = h * HEADDIM + (j - 192); }
        else               { lkind[k] = 2; loff[k] = 2 * DINNER + 2 * NHEADS * DSTATE + h; }
    }
#pragma unroll
    for (int k = 0; k < 9; k++) {
        if (lvalid[k]) {
            const size_t m = (size_t)b * SEQ + lts[k];
            float v;
            if (lkind[k] == 0) v = xbc[m * CONVDIM + loff[k]];
            else               v = zx[m * DPROJ + loff[k]];
            if (lkind[k] == 2) v = 1.f / (1.f + expf(v));
            sd[0][lsh[k]] = v;
        }
    }
    __syncthreads();

    float st[16];
#pragma unroll
    for (int i = 0; i < 16; i++) st[i] = 0.f;
    const float Dh = Dv[h];
    const float zbias = zb[h * HEADDIM + p];

    const int NC = SEQ / CHK;
    for (int c = 0; c < NC; c++) {
        const int cur = c & 1;
        const bool pre = (c + 1 < NC);
        float regv[9];
        if (pre) {
#pragma unroll
            for (int k = 0; k < 9; k++) {
                if (lvalid[k]) {
                    const size_t m = (size_t)b * SEQ + (c + 1) * CHK + lts[k];
                    float v;
                    if (lkind[k] == 0) v = xbc[m * CONVDIM + loff[k]];
                    else               v = zx[m * DPROJ + loff[k]];
                    if (lkind[k] == 2) v = 1.f / (1.f + expf(v));
                    regv[k] = v;
                }
            }
        }
        const float* dbase = sd[cur];
#pragma unroll
        for (int tsub = 0; tsub < CHK; tsub++) {
            const float* dd = dbase + tsub * TVALS;
            const float a  = dd[256];
            const float xv = dd[p];
            float y = 0.f;
#pragma unroll
            for (int i = 0; i < 16; i++) {
                st[i] = a * st[i] + xv * dd[64 + n0 + i];
                y = fmaf(st[i], dd[128 + n0 + i], y);
            }
            y += __shfl_xor_sync(0xffffffffu, y, 1);
            y += __shfl_xor_sync(0xffffffffu, y, 2);
            if (q == 0) {
                const size_t m = (size_t)b * SEQ + c * CHK + tsub;
                const float zval = dd[192 + p] + zbias;
                const float sig = 1.f / (1.f + expf(-zval));
                gated[m * DMODEL + h * HEADDIM + p] = (y + Dh * xv) * (zval * sig);
            }
        }
        if (pre) {
#pragma unroll
            for (int k = 0; k < 9; k++)
                if (lvalid[k]) sd[cur ^ 1][lsh[k]] = regv[k];
        }
        __syncthreads();
    }
}

// ---------------- silu(gate)*up in place ----------------
__global__ void silumul_kernel(float* __restrict__ g, const float* __restrict__ u, size_t n)
{
    size_t i = (size_t)blockIdx.x * blockDim.x + threadIdx.x;
    const size_t stride = (size_t)gridDim.x * blockDim.x;
    for (; i < n; i += stride) {
        const float x = g[i];
        g[i] = u[i] * x / (1.f + expf(-x));
    }
}

// ---------------- launcher ----------------
extern "C" void kernel_launch(void* const* d_in, const int* in_sizes, int n_in,
                              void* d_out, int out_size)
{
    (void)in_sizes; (void)n_in; (void)out_size;
    const float* hidden     = (const float*)d_in[0];
    const float* mask       = (const float*)d_in[1];
    const float* in_proj_w  = (const float*)d_in[2];
    const float* conv_w     = (const float*)d_in[3];
    const float* conv_b     = (const float*)d_in[4];
    const float* z_bias     = (const float*)d_in[5];
    const float* Dv         = (const float*)d_in[6];
    const float* out_proj_w = (const float*)d_in[7];
    const float* ln1_w      = (const float*)d_in[8];
    const float* ln2_w      = (const float*)d_in[9];
    const float* gate_w     = (const float*)d_in[10];
    const float* up_w       = (const float*)d_in[11];
    const float* down_w     = (const float*)d_in[12];
    float* out = (float*)d_out;

    float *xnorm, *zx, *xbc, *gated, *res2, *gatef, *upf;
    cudaGetSymbolAddress((void**)&xnorm, g_xnorm);
    cudaGetSymbolAddress((void**)&zx,    g_zx);
    cudaGetSymbolAddress((void**)&xbc,   g_xbc);
    cudaGetSymbolAddress((void**)&gated, g_gated);
    cudaGetSymbolAddress((void**)&res2,  g_res2);
    cudaGetSymbolAddress((void**)&gatef, g_gatef);
    cudaGetSymbolAddress((void**)&upf,   g_upf);

    cudaFuncSetAttribute(gemm_mma, cudaFuncAttributeMaxDynamicSharedMemorySize, GSMEM);

    // 1. rmsnorm(hidden, ln1) * mask
    rmsnorm_kernel<<<MROWS, 256>>>(hidden, ln1_w, mask, xnorm);

    // 2. zxbcdt = xnorm @ in_proj_w^T   (4096 x 8224 x 2048)
    gemm_mma<<<dim3(MROWS/128, (DPROJ + 255)/256), 256, GSMEM>>>(
        xnorm, in_proj_w, zx, nullptr, DPROJ, DMODEL, 0);

    // 3. conv + 4. scan (fused D*x + silu(z) gate)
    conv_kernel<<<MROWS, 256>>>(zx, conv_w, conv_b, xbc);
    scan_kernel<<<BATCH * NHEADS, 256>>>(xbc, zx, Dv, z_bias, gated);

    // 5. res2 = gated @ out_proj_w^T + hidden
    gemm_mma<<<dim3(MROWS/128, DMODEL/256), 256, GSMEM>>>(
        gated, out_proj_w, res2, hidden, DMODEL, DMODEL, 1);

    // 6. h2n = rmsnorm(res2, ln2)  (reuse xnorm buffer)
    rmsnorm_kernel<<<MROWS, 256>>>(res2, ln2_w, nullptr, xnorm);

    // 7/8. gate and up projections (4096 x 5504 x 2048)
    gemm_mma<<<dim3(MROWS/128, (INTERSZ + 255)/256), 256, GSMEM>>>(
        xnorm, gate_w, gatef, nullptr, INTERSZ, DMODEL, 0);
    gemm_mma<<<dim3(MROWS/128, (INTERSZ + 255)/256), 256, GSMEM>>>(
        xnorm, up_w, upf, nullptr, INTERSZ, DMODEL, 0);

    // 9. gate = silu(gate) * up
    silumul_kernel<<<8192, 256>>>(gatef, upf, (size_t)MROWS * INTERSZ);

    // 10. out = gate @ down_w^T + res2   (4096 x 2048 x 5504)
    gemm_mma<<<dim3(MROWS/128, DMODEL/256), 256, GSMEM>>>(
        gatef, down_w, out, res2, DMODEL, INTERSZ, 1);
}

// round 6
// speedup vs baseline: 1.3048x; 1.3048x over previous
#include <cuda_runtime.h>
#include <cuda_bf16.h>
#include <math.h>
#include <stdint.h>

#define BATCH   2
#define SEQ     2048
#define DMODEL  2048
#define NHEADS  32
#define DSTATE  64
#define HEADDIM 64
#define DCONV   4
#define INTERSZ 5504
#define DINNER  DMODEL
#define CONVDIM (DINNER + 2*NHEADS*DSTATE)              /* 6144 */
#define DPROJ   (2*DINNER + 2*NHEADS*DSTATE + NHEADS)   /* 8224 */
#define MROWS   (BATCH*SEQ)                             /* 4096 */

// ---------------- scratch ----------------
__device__ float g_xnorm[(size_t)MROWS * DMODEL];
__device__ float g_zx   [(size_t)MROWS * DPROJ];
__device__ float g_xbc  [(size_t)MROWS * CONVDIM];
__device__ float g_gated[(size_t)MROWS * DMODEL];
__device__ float g_res2 [(size_t)MROWS * DMODEL];
__device__ float g_gatef[(size_t)MROWS * INTERSZ];
__device__ float g_upf  [(size_t)MROWS * INTERSZ];
// packed bf16 hi/lo tile images: tile = 128 rows x 32 cols, 80B rows, hi plane
// (10240 B) then lo plane (10240 B) => 20480 B per (tile,slab).
__device__ __align__(128) uint8_t g_pa[(size_t)32 * 172 * 20480];  /* 113 MB */
__device__ __align__(128) uint8_t g_pb[(size_t)65 * 64  * 20480];  /* 85 MB  */

static __device__ __forceinline__ uint32_t smem_u32(const void* p) {
    uint32_t a;
    asm("{ .reg .u64 t; cvta.to.shared.u64 t, %1; cvt.u32.u64 %0, t; }" : "=r"(a) : "l"(p));
    return a;
}

#define LDSM_X4(r, addr) \
    asm volatile("ldmatrix.sync.aligned.m8n8.x4.shared.b16 {%0,%1,%2,%3}, [%4];" \
        : "=r"((r)[0]), "=r"((r)[1]), "=r"((r)[2]), "=r"((r)[3]) : "r"(addr))

#define MMA16816(c, a, b0, b1) \
    asm volatile("mma.sync.aligned.m16n8k16.row.col.f32.bf16.bf16.f32 " \
        "{%0,%1,%2,%3}, {%4,%5,%6,%7}, {%8,%9}, {%0,%1,%2,%3};" \
        : "+f"((c)[0]), "+f"((c)[1]), "+f"((c)[2]), "+f"((c)[3]) \
        : "r"((a)[0]), "r"((a)[1]), "r"((a)[2]), "r"((a)[3]), "r"(b0), "r"(b1))

#define CPASYNC16(dst, src) \
    asm volatile("cp.async.cg.shared.global [%0], [%1], 16;" :: "r"(dst), "l"(src))

// ---------------- pack: fp32 -> bf16 hi/lo padded tile images ----------------
// One thread handles 8 consecutive cols of one row of one (tile,slab).
__global__ void pack_tiles(const float* __restrict__ src, uint8_t* __restrict__ dst,
                           int K, int nslab, int Nreal, int nChunks)
{
    for (int id = blockIdx.x * blockDim.x + threadIdx.x; id < nChunks;
         id += gridDim.x * blockDim.x) {
        const int tile = id >> 9;
        const int w = id & 511;
        const int r = w >> 2, g = w & 3;
        const int mt = tile / nslab;
        const int s  = tile - mt * nslab;
        const int row = mt * 128 + r;
        float v[8] = {0.f,0.f,0.f,0.f,0.f,0.f,0.f,0.f};
        if (row < Nreal) {
            const float* p = src + (size_t)row * K + s * 32 + g * 8;
            *(float4*)&v[0] = *(const float4*)p;
            *(float4*)&v[4] = *(const float4*)(p + 4);
        }
        uint32_t hi[4], lo[4];
#pragma unroll
        for (int j = 0; j < 4; j++) {
            __nv_bfloat162 h = __float22bfloat162_rn(make_float2(v[2*j], v[2*j+1]));
            float g0 = __bfloat162float(h.x), g1 = __bfloat162float(h.y);
            __nv_bfloat162 l = __float22bfloat162_rn(make_float2(v[2*j]-g0, v[2*j+1]-g1));
            hi[j] = *(uint32_t*)&h; lo[j] = *(uint32_t*)&l;
        }
        uint8_t* base = dst + (size_t)tile * 20480 + r * 80 + g * 16;
        *(uint4*)base            = *(uint4*)hi;
        *(uint4*)(base + 10240)  = *(uint4*)lo;
    }
}

// ================= bf16x3 GEMM, packed operands, cp.async pipeline =================
// stage: Ahi(10240) Alo(10240) Bhi(10240) Blo(10240) = 40960 B; 2 stages.
#define OFF_AL 10240
#define OFF_BH 20480
#define OFF_BL 30720
#define STAGE  40960
#define GSMEM  (2*STAGE)

__global__ __launch_bounds__(256, 2) void gemm_mma(
    const uint8_t* __restrict__ Ap, const uint8_t* __restrict__ Bp,
    float* __restrict__ C, const float* __restrict__ addv,
    int N, int nslab, int addflag)
{
    extern __shared__ char sm[];
    const int tid  = threadIdx.x;
    const int warp = tid >> 5, lane = tid & 31;
    const int wm = warp >> 2, wn = warp & 3;       // 2 x 4 warps, warp tile 64x32
    const uint32_t sbase = smem_u32(sm);

    const uint8_t* aT = Ap + (size_t)blockIdx.x * nslab * 20480;
    const uint8_t* bT = Bp + (size_t)blockIdx.y * nslab * 20480;

    float acc[4][4][4];
#pragma unroll
    for (int i = 0; i < 4; i++)
#pragma unroll
        for (int j = 0; j < 4; j++)
#pragma unroll
            for (int r = 0; r < 4; r++) acc[i][j][r] = 0.f;

    // prologue: stage 0
    {
        const uint32_t d = sbase;
#pragma unroll
        for (int j = 0; j < 5; j++) {
            const uint32_t cid = (uint32_t)tid * 16 + (uint32_t)j * 4096;
            CPASYNC16(d + cid,         aT + cid);
            CPASYNC16(d + 20480 + cid, bT + cid);
        }
        asm volatile("cp.async.commit_group;" ::: "memory");
    }

    const int lrow  = lane & 15;
    const int lcolb = (lane >> 4) << 3;

    for (int s = 0; s < nslab; s++) {
        asm volatile("cp.async.wait_group 0;" ::: "memory");
        __syncthreads();
        if (s + 1 < nslab) {
            const uint32_t d = sbase + (uint32_t)((s + 1) & 1) * STAGE;
            const uint8_t* an = aT + (size_t)(s + 1) * 20480;
            const uint8_t* bn = bT + (size_t)(s + 1) * 20480;
#pragma unroll
            for (int j = 0; j < 5; j++) {
                const uint32_t cid = (uint32_t)tid * 16 + (uint32_t)j * 4096;
                CPASYNC16(d + cid,         an + cid);
                CPASYNC16(d + 20480 + cid, bn + cid);
            }
            asm volatile("cp.async.commit_group;" ::: "memory");
        }
        const uint32_t stb = sbase + (uint32_t)(s & 1) * STAGE;
#pragma unroll
        for (int ks = 0; ks < 2; ks++) {
            const int k0 = ks * 16;
            uint32_t bh[2][4], bl[2][4];
#pragma unroll
            for (int bt = 0; bt < 2; bt++) {
                const uint32_t off = (uint32_t)(((wn*32 + bt*16 + lrow) * 40 + k0 + lcolb) * 2);
                LDSM_X4(bh[bt], stb + OFF_BH + off);
                LDSM_X4(bl[bt], stb + OFF_BL + off);
            }
#pragma unroll
            for (int mt = 0; mt < 4; mt++) {
                uint32_t ah[4], al[4];
                const uint32_t off = (uint32_t)(((wm*64 + mt*16 + lrow) * 40 + k0 + lcolb) * 2);
                LDSM_X4(ah, stb + off);
                LDSM_X4(al, stb + OFF_AL + off);
#pragma unroll
                for (int nt = 0; nt < 4; nt++) {
                    const int bt = nt >> 1, sel = nt & 1;
                    const uint32_t b0h = bh[bt][sel], b1h = bh[bt][2+sel];
                    const uint32_t b0l = bl[bt][sel], b1l = bl[bt][2+sel];
                    MMA16816(acc[mt][nt], ah, b0h, b1h);
                    MMA16816(acc[mt][nt], al, b0h, b1h);
                    MMA16816(acc[mt][nt], ah, b0l, b1l);
                }
            }
        }
        __syncthreads();
    }

    // ---- epilogue ----
    const int g  = lane >> 2;
    const int t4 = lane & 3;
    const int bm = blockIdx.x * 128, bn = blockIdx.y * 128;
#pragma unroll
    for (int mt = 0; mt < 4; mt++) {
        const int row = bm + wm*64 + mt*16 + g;
#pragma unroll
        for (int nt = 0; nt < 4; nt++) {
            const int col = bn + wn*32 + nt*8 + t4*2;
            if (col < N) {
                float2 v0 = make_float2(acc[mt][nt][0], acc[mt][nt][1]);
                float2 v1 = make_float2(acc[mt][nt][2], acc[mt][nt][3]);
                const size_t i0 = (size_t)row * N + col;
                const size_t i1 = (size_t)(row + 8) * N + col;
                if (addflag) {
                    const float2 a0 = *(const float2*)(addv + i0);
                    const float2 a1 = *(const float2*)(addv + i1);
                    v0.x += a0.x; v0.y += a0.y; v1.x += a1.x; v1.y += a1.y;
                }
                *(float2*)(C + i0) = v0;
                *(float2*)(C + i1) = v1;
            }
        }
    }
}

// ---------------- RMSNorm (optionally * mask) ----------------
__global__ void rmsnorm_kernel(const float* __restrict__ x,
                               const float* __restrict__ w,
                               const float* __restrict__ mask,
                               float* __restrict__ out)
{
    const int m = blockIdx.x;
    const float* row = x + (size_t)m * DMODEL;
    float s = 0.f;
    for (int i = threadIdx.x; i < DMODEL; i += 256) { float v = row[i]; s += v * v; }
#pragma unroll
    for (int o = 16; o > 0; o >>= 1) s += __shfl_xor_sync(0xffffffffu, s, o);
    __shared__ float red[8];
    const int lane = threadIdx.x & 31, wid = threadIdx.x >> 5;
    if (lane == 0) red[wid] = s;
    __syncthreads();
    if (wid == 0) {
        s = (lane < 8) ? red[lane] : 0.f;
#pragma unroll
        for (int o = 4; o > 0; o >>= 1) s += __shfl_xor_sync(0xffffffffu, s, o);
        if (lane == 0) red[0] = s;
    }
    __syncthreads();
    const float inv = rsqrtf(red[0] * (1.0f / (float)DMODEL) + 1e-6f);
    const float mk = mask ? mask[m] : 1.f;
    for (int i = threadIdx.x; i < DMODEL; i += 256)
        out[(size_t)m * DMODEL + i] = row[i] * inv * w[i] * mk;
}

// ---------------- causal depthwise conv1d ----------------
__global__ void conv_kernel(const float* __restrict__ zx,
                            const float* __restrict__ cw,
                            const float* __restrict__ cb,
                            float* __restrict__ xbc)
{
    const int m = blockIdx.x;
    const int t = m & (SEQ - 1);
    for (int c = threadIdx.x; c < CONVDIM; c += 256) {
        float acc = cb[c];
#pragma unroll
        for (int j = 0; j < DCONV; j++) {
            const int tt = t - (DCONV - 1) + j;
            if (tt >= 0)
                acc += cw[c * DCONV + j] *
                       zx[(size_t)(m - (DCONV - 1) + j) * DPROJ + DINNER + c];
        }
        xbc[(size_t)m * CONVDIM + c] = acc;
    }
}

// ---------------- sequential SSM scan + gating ----------------
#define CHK 8
#define TVALS 257
__global__ __launch_bounds__(256) void scan_kernel(
    const float* __restrict__ xbc, const float* __restrict__ zx,
    const float* __restrict__ Dv, const float* __restrict__ zb,
    float* __restrict__ gated)
{
    const int bh = blockIdx.x;
    const int b = bh >> 5;
    const int h = bh & 31;
    const int tid = threadIdx.x;
    const int p = tid >> 2;
    const int q = tid & 3;
    const int n0 = q << 4;

    __shared__ float sd[2][CHK * TVALS];

    int lts[9], loff[9], lkind[9], lsh[9];
    bool lvalid[9];
#pragma unroll
    for (int k = 0; k < 9; k++) {
        const int e = tid + k * 256;
        lvalid[k] = (e < CHK * TVALS);
        const int tsub = e / TVALS;
        const int j = e - tsub * TVALS;
        lts[k] = tsub; lsh[k] = e;
        if (j < 64)        { lkind[k] = 0; loff[k] = h * HEADDIM + j; }
        else if (j < 128)  { lkind[k] = 0; loff[k] = DINNER + h * DSTATE + (j - 64); }
        else if (j < 192)  { lkind[k] = 0; loff[k] = DINNER + NHEADS * DSTATE + h * DSTATE + (j - 128); }
        else if (j < 256)  { lkind[k] = 1; loff[k] = h * HEADDIM + (j - 192); }
        else               { lkind[k] = 2; loff[k] = 2 * DINNER + 2 * NHEADS * DSTATE + h; }
    }
#pragma unroll
    for (int k = 0; k < 9; k++) {
        if (lvalid[k]) {
            const size_t m = (size_t)b * SEQ + lts[k];
            float v;
            if (lkind[k] == 0) v = xbc[m * CONVDIM + loff[k]];
            else               v = zx[m * DPROJ + loff[k]];
            if (lkind[k] == 2) v = 1.f / (1.f + expf(v));
            sd[0][lsh[k]] = v;
        }
    }
    __syncthreads();

    float st[16];
#pragma unroll
    for (int i = 0; i < 16; i++) st[i] = 0.f;
    const float Dh = Dv[h];
    const float zbias = zb[h * HEADDIM + p];

    const int NC = SEQ / CHK;
    for (int c = 0; c < NC; c++) {
        const int cur = c & 1;
        const bool pre = (c + 1 < NC);
        float regv[9];
        if (pre) {
#pragma unroll
            for (int k = 0; k < 9; k++) {
                if (lvalid[k]) {
                    const size_t m = (size_t)b * SEQ + (c + 1) * CHK + lts[k];
                    float v;
                    if (lkind[k] == 0) v = xbc[m * CONVDIM + loff[k]];
                    else               v = zx[m * DPROJ + loff[k]];
                    if (lkind[k] == 2) v = 1.f / (1.f + expf(v));
                    regv[k] = v;
                }
            }
        }
        const float* dbase = sd[cur];
#pragma unroll
        for (int tsub = 0; tsub < CHK; tsub++) {
            const float* dd = dbase + tsub * TVALS;
            const float a  = dd[256];
            const float xv = dd[p];
            float y = 0.f;
#pragma unroll
            for (int i = 0; i < 16; i++) {
                st[i] = a * st[i] + xv * dd[64 + n0 + i];
                y = fmaf(st[i], dd[128 + n0 + i], y);
            }
            y += __shfl_xor_sync(0xffffffffu, y, 1);
            y += __shfl_xor_sync(0xffffffffu, y, 2);
            if (q == 0) {
                const size_t m = (size_t)b * SEQ + c * CHK + tsub;
                const float zval = dd[192 + p] + zbias;
                const float sig = 1.f / (1.f + expf(-zval));
                gated[m * DMODEL + h * HEADDIM + p] = (y + Dh * xv) * (zval * sig);
            }
        }
        if (pre) {
#pragma unroll
            for (int k = 0; k < 9; k++)
                if (lvalid[k]) sd[cur ^ 1][lsh[k]] = regv[k];
        }
        __syncthreads();
    }
}

// ---------------- silu(gate)*up in place ----------------
__global__ void silumul_kernel(float* __restrict__ g, const float* __restrict__ u, size_t n)
{
    size_t i = (size_t)blockIdx.x * blockDim.x + threadIdx.x;
    const size_t stride = (size_t)gridDim.x * blockDim.x;
    for (; i < n; i += stride) {
        const float x = g[i];
        g[i] = u[i] * x / (1.f + expf(-x));
    }
}

// ---------------- launcher ----------------
extern "C" void kernel_launch(void* const* d_in, const int* in_sizes, int n_in,
                              void* d_out, int out_size)
{
    (void)in_sizes; (void)n_in; (void)out_size;
    const float* hidden     = (const float*)d_in[0];
    const float* mask       = (const float*)d_in[1];
    const float* in_proj_w  = (const float*)d_in[2];
    const float* conv_w     = (const float*)d_in[3];
    const float* conv_b     = (const float*)d_in[4];
    const float* z_bias     = (const float*)d_in[5];
    const float* Dv         = (const float*)d_in[6];
    const float* out_proj_w = (const float*)d_in[7];
    const float* ln1_w      = (const float*)d_in[8];
    const float* ln2_w      = (const float*)d_in[9];
    const float* gate_w     = (const float*)d_in[10];
    const float* up_w       = (const float*)d_in[11];
    const float* down_w     = (const float*)d_in[12];
    float* out = (float*)d_out;

    float *xnorm, *zx, *xbc, *gated, *res2, *gatef, *upf;
    uint8_t *pa, *pb;
    cudaGetSymbolAddress((void**)&xnorm, g_xnorm);
    cudaGetSymbolAddress((void**)&zx,    g_zx);
    cudaGetSymbolAddress((void**)&xbc,   g_xbc);
    cudaGetSymbolAddress((void**)&gated, g_gated);
    cudaGetSymbolAddress((void**)&res2,  g_res2);
    cudaGetSymbolAddress((void**)&gatef, g_gatef);
    cudaGetSymbolAddress((void**)&upf,   g_upf);
    cudaGetSymbolAddress((void**)&pa,    g_pa);
    cudaGetSymbolAddress((void**)&pb,    g_pb);

    cudaFuncSetAttribute(gemm_mma, cudaFuncAttributeMaxDynamicSharedMemorySize, GSMEM);
    const int PKG = 4096;

    // ---- mixer ----
    rmsnorm_kernel<<<MROWS, 256>>>(hidden, ln1_w, mask, xnorm);
    pack_tiles<<<PKG, 256>>>(xnorm, pa, 2048, 64, MROWS, 32*64*512);
    pack_tiles<<<PKG, 256>>>(in_proj_w, pb, 2048, 64, DPROJ, 65*64*512);
    gemm_mma<<<dim3(32, 65), 256, GSMEM>>>(pa, pb, zx, nullptr, DPROJ, 64, 0);

    conv_kernel<<<MROWS, 256>>>(zx, conv_w, conv_b, xbc);
    scan_kernel<<<BATCH * NHEADS, 256>>>(xbc, zx, Dv, z_bias, gated);

    pack_tiles<<<PKG, 256>>>(gated, pa, 2048, 64, MROWS, 32*64*512);
    pack_tiles<<<PKG, 256>>>(out_proj_w, pb, 2048, 64, DMODEL, 16*64*512);
    gemm_mma<<<dim3(32, 16), 256, GSMEM>>>(pa, pb, res2, hidden, DMODEL, 64, 1);

    // ---- MLP ----
    rmsnorm_kernel<<<MROWS, 256>>>(res2, ln2_w, nullptr, xnorm);
    pack_tiles<<<PKG, 256>>>(xnorm, pa, 2048, 64, MROWS, 32*64*512);
    pack_tiles<<<PKG, 256>>>(gate_w, pb, 2048, 64, INTERSZ, 43*64*512);
    gemm_mma<<<dim3(32, 43), 256, GSMEM>>>(pa, pb, gatef, nullptr, INTERSZ, 64, 0);
    pack_tiles<<<PKG, 256>>>(up_w, pb, 2048, 64, INTERSZ, 43*64*512);
    gemm_mma<<<dim3(32, 43), 256, GSMEM>>>(pa, pb, upf, nullptr, INTERSZ, 64, 0);
    silumul_kernel<<<8192, 256>>>(gatef, upf, (size_t)MROWS * INTERSZ);
    pack_tiles<<<PKG, 256>>>(gatef, pa, 5504, 172, MROWS, 32*172*512);
    pack_tiles<<<PKG, 256>>>(down_w, pb, 5504, 172, DMODEL, 16*172*512);
    gemm_mma<<<dim3(32, 16), 256, GSMEM>>>(pa, pb, out, res2, DMODEL, 172, 1);
}